// round 3
// baseline (speedup 1.0000x reference)
#include <cuda_runtime.h>
#include <cstddef>

// ---------------- problem constants ----------------
constexpr int cB   = 512;
constexpr int cN   = 128;
constexpr int cFIN = 133;
constexpr int cD   = 64;    // NHID
constexpr int cH   = 8;     // NHEADS
constexpr int cHID = 512;
constexpr int cFPD = 1489;
constexpr int cTASKS = 12;
#define ALPHA_F 0.2f
#define NEG_BIG_F (-9e15f)

// ---------------- scratch (static device globals; no allocs) ----------------
__device__ float g_Wh[cB * cH * cN * cD];     // 128 MB
__device__ float g_s1[cB * cH * cN];
__device__ float g_s2[cB * cH * cN];
__device__ float g_x [cB * cN * cHID];        // 128 MB
__device__ float g_Wx[cB * cN * cHID];        // 128 MB
__device__ float g_t1[cB * cN];
__device__ float g_t2[cB * cN];
__device__ float g_gat[cB * cHID];
__device__ float g_fp1[cB * cHID];
__device__ float g_fpn[cB * cHID];
__device__ float g_fused[cB * cHID];
__device__ float g_z1[cB * cHID];
__device__ float g_z2[cB * cHID];

__device__ __forceinline__ float lrelu(float x) { return x >= 0.f ? x : ALPHA_F * x; }
__device__ __forceinline__ float eluf (float x) { return x >  0.f ? x : expm1f(x); }

// ============================================================================
// Kernel 1: Wh[b,h,n,d] = h[b,n,:] @ W_heads[h]; fused s1,s2 head reductions.
// Block = 512 threads handles 8 (b,n) rows; thread (hh,d) accumulates 8 rows.
// ============================================================================
__global__ __launch_bounds__(512) void k_wh(
    const float* __restrict__ hin, const float* __restrict__ W,
    const float* __restrict__ a1, const float* __restrict__ a2)
{
    __shared__ float sh[8][cFIN];
    __shared__ float red1[8][16], red2[8][16];
    const int row0 = blockIdx.x * 8;
    const int tid = threadIdx.x;

    for (int idx = tid; idx < 8 * cFIN; idx += 512) {
        int r = idx / cFIN, f = idx % cFIN;
        sh[r][f] = hin[(size_t)(row0 + r) * cFIN + f];
    }
    __syncthreads();

    const int hh = tid >> 6, d = tid & 63;
    float acc[8];
#pragma unroll
    for (int r = 0; r < 8; r++) acc[r] = 0.f;

    const float* Wp = W + (size_t)hh * cFIN * cD + d;
    for (int f = 0; f < cFIN; f++) {
        float w = Wp[(size_t)f * cD];
#pragma unroll
        for (int r = 0; r < 8; r++) acc[r] += sh[r][f] * w;
    }

    const float a1v = a1[hh * cD + d], a2v = a2[hh * cD + d];
    const int wrp = tid >> 5, lane = tid & 31;
#pragma unroll
    for (int r = 0; r < 8; r++) {
        int row = row0 + r;
        int b = row >> 7, n = row & 127;
        g_Wh[(((size_t)(b * cH + hh) * cN + n) << 6) + d] = acc[r];
        float v1 = acc[r] * a1v, v2 = acc[r] * a2v;
#pragma unroll
        for (int off = 16; off; off >>= 1) {
            v1 += __shfl_down_sync(0xffffffffu, v1, off);
            v2 += __shfl_down_sync(0xffffffffu, v2, off);
        }
        if (lane == 0) { red1[r][wrp] = v1; red2[r][wrp] = v2; }
    }
    __syncthreads();
    if (tid < 64) {
        int r = tid >> 3, h2 = tid & 7;
        int row = row0 + r;
        int b = row >> 7, n = row & 127;
        g_s1[(b * cH + h2) * cN + n] = red1[r][2 * h2] + red1[r][2 * h2 + 1];
        g_s2[(b * cH + h2) * cN + n] = red2[r][2 * h2] + red2[r][2 * h2 + 1];
    }
}

// ============================================================================
// Kernel 2: per (b,h): masked softmax over e = leaky(s1_i + s2_j + edge*ae),
// hp = att @ Wh, x[b,i,h*64+d] = elu(hp). One block per (b,h), 256 threads.
// ============================================================================
__global__ __launch_bounds__(256) void k_attn1(
    const float* __restrict__ edge, const int* __restrict__ adj,
    const float* __restrict__ ae)
{
    __shared__ float s1r[cN], s2r[cN];
    __shared__ float att_s[8][cN];
    __shared__ float whs[cN * cD];

    const int bid = blockIdx.x;
    const int b = bid >> 3, hh = bid & 7;
    const int tid = threadIdx.x, wrp = tid >> 5, lane = tid & 31;

    const float* whg = g_Wh + ((size_t)(b * cH + hh) * cN << 6);
    if (tid < cN) {
        s1r[tid] = g_s1[(b * cH + hh) * cN + tid];
        s2r[tid] = g_s2[(b * cH + hh) * cN + tid];
    }
    for (int idx = tid; idx < cN * cD; idx += 256) whs[idx] = whg[idx];
    __syncthreads();

    const float aev = ae[hh];
    const float2* whs2 = (const float2*)whs;

    for (int it = 0; it < 16; it++) {
        const int i = wrp * 16 + it;
        const float* erow = edge + ((size_t)b * cN + i) * cN;
        const int*   arow = adj  + ((size_t)b * cN + i) * cN;
        const float s1v = s1r[i];
        float val[4];
        float mx = -3.4e38f;
#pragma unroll
        for (int k = 0; k < 4; k++) {
            int j = lane + 32 * k;
            float v = (arow[j] > 0) ? lrelu(s1v + s2r[j] + erow[j] * aev) : NEG_BIG_F;
            val[k] = v; mx = fmaxf(mx, v);
        }
#pragma unroll
        for (int off = 16; off; off >>= 1) mx = fmaxf(mx, __shfl_xor_sync(0xffffffffu, mx, off));
        float sum = 0.f;
#pragma unroll
        for (int k = 0; k < 4; k++) { val[k] = __expf(val[k] - mx); sum += val[k]; }
#pragma unroll
        for (int off = 16; off; off >>= 1) sum += __shfl_xor_sync(0xffffffffu, sum, off);
        const float inv = 1.f / sum;
#pragma unroll
        for (int k = 0; k < 4; k++) att_s[wrp][lane + 32 * k] = val[k] * inv;
        __syncwarp();

        float acc0 = 0.f, acc1 = 0.f;
#pragma unroll 8
        for (int j = 0; j < cN; j++) {
            float a = att_s[wrp][j];
            float2 wv = whs2[(j << 5) + lane];
            acc0 += a * wv.x; acc1 += a * wv.y;
        }
        float2 o; o.x = eluf(acc0); o.y = eluf(acc1);
        ((float2*)g_x)[(size_t)(b * cN + i) * (cHID / 2) + hh * 32 + lane] = o;
        __syncwarp();
    }
}

// ============================================================================
// Generic SGEMM: C[M,N] = act(A[M,K] @ B[K,N] + bias (+ C if accum)).
// 128x128 block tile, 256 threads, 8x8 microtile, K-step 8.
// ============================================================================
__global__ __launch_bounds__(256) void sgemm_k(
    const float* __restrict__ A, const float* __restrict__ Bm,
    const float* __restrict__ bias, float* __restrict__ C,
    int M, int Ncols, int K, int act, int accum)
{
    __shared__ float As[8][128];
    __shared__ float Bs[8][128];
    const int m0 = blockIdx.y * 128, n0 = blockIdx.x * 128;
    const int t = threadIdx.x;
    const int tx = t & 15, ty = t >> 4;

    float acc[8][8];
#pragma unroll
    for (int i = 0; i < 8; i++)
#pragma unroll
        for (int j = 0; j < 8; j++) acc[i][j] = 0.f;

    for (int k0 = 0; k0 < K; k0 += 8) {
#pragma unroll
        for (int i = 0; i < 4; i++) {
            int idx = t + i * 256;
            int m = idx >> 3, kk = idx & 7;
            int gm = m0 + m, gk = k0 + kk;
            As[kk][m] = (gm < M && gk < K) ? A[(size_t)gm * K + gk] : 0.f;
        }
#pragma unroll
        for (int i = 0; i < 4; i++) {
            int idx = t + i * 256;
            int kk = idx >> 7, n = idx & 127;
            int gk = k0 + kk, gn = n0 + n;
            Bs[kk][n] = (gk < K && gn < Ncols) ? Bm[(size_t)gk * Ncols + gn] : 0.f;
        }
        __syncthreads();
#pragma unroll
        for (int kk = 0; kk < 8; kk++) {
            float a[8], bb[8];
#pragma unroll
            for (int i = 0; i < 8; i++) a[i] = As[kk][ty * 8 + i];
#pragma unroll
            for (int j = 0; j < 8; j++) bb[j] = Bs[kk][tx * 8 + j];
#pragma unroll
            for (int i = 0; i < 8; i++)
#pragma unroll
                for (int j = 0; j < 8; j++) acc[i][j] += a[i] * bb[j];
        }
        __syncthreads();
    }

#pragma unroll
    for (int i = 0; i < 8; i++) {
        int gm = m0 + ty * 8 + i;
        if (gm >= M) continue;
#pragma unroll
        for (int j = 0; j < 8; j++) {
            int gn = n0 + tx * 8 + j;
            if (gn >= Ncols) continue;
            float v = acc[i][j];
            if (bias) v += bias[gn];
            if (accum) v += C[(size_t)gm * Ncols + gn];
            if (act == 1) v = fmaxf(v, 0.f);
            C[(size_t)gm * Ncols + gn] = v;
        }
    }
}

// ============================================================================
// Kernel: t1[row] = Wx[row,:]·a1_out ; t2 likewise. One warp per row.
// ============================================================================
__global__ __launch_bounds__(256) void k_t12(
    const float* __restrict__ a1o, const float* __restrict__ a2o)
{
    const int wrp = threadIdx.x >> 5, lane = threadIdx.x & 31;
    const int row = blockIdx.x * 8 + wrp;
    const float* x = g_Wx + (size_t)row * cHID;
    float t1 = 0.f, t2 = 0.f;
    for (int k = lane; k < cHID; k += 32) {
        float v = x[k];
        t1 += v * a1o[k]; t2 += v * a2o[k];
    }
#pragma unroll
    for (int off = 16; off; off >>= 1) {
        t1 += __shfl_down_sync(0xffffffffu, t1, off);
        t2 += __shfl_down_sync(0xffffffffu, t2, off);
    }
    if (lane == 0) { g_t1[row] = t1; g_t2[row] = t2; }
}

// ============================================================================
// Kernel 4: per b: masked softmax on e2, hp2 = att2 @ Wx[b], elu, mean over N
// -> gat_out[b,:]. One block per b, 256 threads, ~99 KB dynamic smem.
// ============================================================================
__global__ __launch_bounds__(256) void k_attn2(
    const float* __restrict__ edge, const int* __restrict__ adj,
    const float* __restrict__ ae_out)
{
    extern __shared__ float dynsm[];
    float* att2 = dynsm;               // 128*128
    float* wxs  = att2 + cN * cN;      // 128*64
    float* t1r  = wxs + cN * 64;       // 128
    float* t2r  = t1r + cN;            // 128
    float* csum = t2r + cN;            // 8*64

    const int b = blockIdx.x;
    const int tid = threadIdx.x, wrp = tid >> 5, lane = tid & 31;

    if (tid < cN) { t1r[tid] = g_t1[b * cN + tid]; t2r[tid] = g_t2[b * cN + tid]; }
    __syncthreads();
    const float aev = ae_out[0];

    for (int it = 0; it < 16; it++) {
        const int i = wrp * 16 + it;
        const float* erow = edge + ((size_t)b * cN + i) * cN;
        const int*   arow = adj  + ((size_t)b * cN + i) * cN;
        const float t1v = t1r[i];
        float val[4];
        float mx = -3.4e38f;
#pragma unroll
        for (int k = 0; k < 4; k++) {
            int j = lane + 32 * k;
            float v = (arow[j] > 0) ? lrelu(t1v + t2r[j] + erow[j] * aev) : NEG_BIG_F;
            val[k] = v; mx = fmaxf(mx, v);
        }
#pragma unroll
        for (int off = 16; off; off >>= 1) mx = fmaxf(mx, __shfl_xor_sync(0xffffffffu, mx, off));
        float sum = 0.f;
#pragma unroll
        for (int k = 0; k < 4; k++) { val[k] = __expf(val[k] - mx); sum += val[k]; }
#pragma unroll
        for (int off = 16; off; off >>= 1) sum += __shfl_xor_sync(0xffffffffu, sum, off);
        const float inv = 1.f / sum;
#pragma unroll
        for (int k = 0; k < 4; k++) att2[i * cN + lane + 32 * k] = val[k] * inv;
    }
    __syncthreads();

    const int c2 = tid & 31, rg = tid >> 5;
    for (int dt = 0; dt < 8; dt++) {
        for (int idx = tid; idx < cN * 64; idx += 256) {
            int j = idx >> 6, c = idx & 63;
            wxs[idx] = g_Wx[(size_t)(b * cN + j) * cHID + dt * 64 + c];
        }
        __syncthreads();
        const float2* wxs2 = (const float2*)wxs;
        float cs0 = 0.f, cs1 = 0.f;
        for (int ii = 0; ii < 16; ii++) {
            const int i = rg * 16 + ii;
            const float* arow = att2 + i * cN;
            float acc0 = 0.f, acc1 = 0.f;
#pragma unroll 8
            for (int j = 0; j < cN; j++) {
                float a = arow[j];
                float2 wv = wxs2[(j << 5) + c2];
                acc0 += a * wv.x; acc1 += a * wv.y;
            }
            cs0 += eluf(acc0); cs1 += eluf(acc1);
        }
        csum[rg * 64 + 2 * c2]     = cs0;
        csum[rg * 64 + 2 * c2 + 1] = cs1;
        __syncthreads();
        if (tid < 64) {
            float tot = 0.f;
#pragma unroll
            for (int r = 0; r < 8; r++) tot += csum[r * 64 + tid];
            g_gat[b * cHID + dt * 64 + tid] = tot * (1.f / 128.f);
        }
        __syncthreads();
    }
}

// ============================================================================
// Host launcher
// ============================================================================
extern "C" void kernel_launch(void* const* d_in, const int* in_sizes, int n_in,
                              void* d_out, int out_size)
{
    const float* hin   = (const float*)d_in[0];
    const int*   adj   = (const int*)  d_in[1];
    const float* edge  = (const float*)d_in[2];
    const float* fp    = (const float*)d_in[3];
    const float* W_h   = (const float*)d_in[4];
    const float* a1_h  = (const float*)d_in[5];
    const float* a2_h  = (const float*)d_in[6];
    const float* ae_h  = (const float*)d_in[7];
    const float* W_out = (const float*)d_in[8];
    const float* a1_o  = (const float*)d_in[9];
    const float* a2_o  = (const float*)d_in[10];
    const float* ae_o  = (const float*)d_in[11];
    const float* fc1w  = (const float*)d_in[12];
    const float* fc1b  = (const float*)d_in[13];
    const float* fc2w  = (const float*)d_in[14];
    const float* fc2b  = (const float*)d_in[15];
    const float* q_w   = (const float*)d_in[16];
    const float* q_b   = (const float*)d_in[17];
    // d_in[18], d_in[19] = k_w, k_b : dead (softmax over size-1 axis == 1)
    const float* v_w   = (const float*)d_in[20];
    const float* v_b   = (const float*)d_in[21];
    const float* o_w   = (const float*)d_in[22];
    const float* o_b   = (const float*)d_in[23];
    const float* f1w   = (const float*)d_in[24];
    const float* f1b   = (const float*)d_in[25];
    const float* f2w   = (const float*)d_in[26];
    const float* f2b   = (const float*)d_in[27];
    float* out = (float*)d_out;

    float *pX, *pWx, *pGat, *pFp1, *pFpn, *pFused, *pZ1, *pZ2;
    cudaGetSymbolAddress((void**)&pX,    g_x);
    cudaGetSymbolAddress((void**)&pWx,   g_Wx);
    cudaGetSymbolAddress((void**)&pGat,  g_gat);
    cudaGetSymbolAddress((void**)&pFp1,  g_fp1);
    cudaGetSymbolAddress((void**)&pFpn,  g_fpn);
    cudaGetSymbolAddress((void**)&pFused,g_fused);
    cudaGetSymbolAddress((void**)&pZ1,   g_z1);
    cudaGetSymbolAddress((void**)&pZ2,   g_z2);

    const int smem_k4 = (cN * cN + cN * 64 + cN + cN + 8 * 64) * (int)sizeof(float);
    cudaFuncSetAttribute(k_attn2, cudaFuncAttributeMaxDynamicSharedMemorySize, smem_k4);

    // 1) Wh + s1/s2
    k_wh<<<(cB * cN) / 8, 512>>>(hin, W_h, a1_h, a2_h);
    // 2) head attention -> x [B,N,512]
    k_attn1<<<cB * cH, 256>>>(edge, adj, ae_h);
    // 3) Wx = x @ W_out  [65536,512]x[512,512]
    {
        dim3 grid(cHID / 128, (cB * cN) / 128);
        sgemm_k<<<grid, 256>>>(pX, W_out, nullptr, pWx, cB * cN, cHID, cHID, 0, 0);
    }
    // 4) t1,t2
    k_t12<<<(cB * cN) / 8, 256>>>(a1_o, a2_o);
    // 5) output attention + ELU + mean -> gat_out [B,512]
    k_attn2<<<cB, 256, smem_k4>>>(edge, adj, ae_o);
    // 6) FPN
    {
        dim3 grid(cHID / 128, cB / 128);
        sgemm_k<<<grid, 256>>>(fp,   fc1w, fc1b, pFp1, cB, cHID, cFPD, 1, 0);
        sgemm_k<<<grid, 256>>>(pFp1, fc2w, fc2b, pFpn, cB, cHID, cHID, 0, 0);
        // 7) fused = (gat@q_w + q_b) + (fpn@v_w + v_b)   [softmax(1)==1]
        sgemm_k<<<grid, 256>>>(pGat, q_w, q_b, pFused, cB, cHID, cHID, 0, 0);
        sgemm_k<<<grid, 256>>>(pFpn, v_w, v_b, pFused, cB, cHID, cHID, 0, 1);
        // 8) z1 = relu(fused @ o_w + o_b)
        sgemm_k<<<grid, 256>>>(pFused, o_w, o_b, pZ1, cB, cHID, cHID, 1, 0);
        // 9) z2 = relu(z1 @ ffn1 + b)
        sgemm_k<<<grid, 256>>>(pZ1, f1w, f1b, pZ2, cB, cHID, cHID, 1, 0);
    }
    // 10) out = z2 @ ffn2 + b   [512,12]
    {
        dim3 grid(1, cB / 128);
        sgemm_k<<<grid, 256>>>(pZ2, f2w, f2b, out, cB, cTASKS, cHID, 0, 0);
    }
}

// round 8
// speedup vs baseline: 1.4121x; 1.4121x over previous
#include <cuda_runtime.h>
#include <cstddef>

constexpr int cB   = 512;
constexpr int cN   = 128;
constexpr int cFIN = 133;
constexpr int cD   = 64;
constexpr int cH   = 8;
constexpr int cHID = 512;
constexpr int cFPD = 1489;
constexpr int cTASKS = 12;
#define ALPHA_F 0.2f
#define NEG_BIG_F (-9e15f)

__device__ float g_Wh[cB * cH * cN * cD];
__device__ float g_s1[cB * cH * cN];
__device__ float g_s2[cB * cH * cN];
__device__ float g_x [cB * cN * cHID];
__device__ float g_Wx[cB * cN * cHID];
__device__ float g_t1[cB * cN];
__device__ float g_t2[cB * cN];
__device__ float g_gat[cB * cHID];
__device__ float g_fp1[cB * cHID];
__device__ float g_fpn[cB * cHID];
__device__ float g_fused[cB * cHID];
__device__ float g_z1[cB * cHID];
__device__ float g_z2[cB * cHID];

__device__ __forceinline__ float lrelu(float x) { return x >= 0.f ? x : ALPHA_F * x; }
__device__ __forceinline__ float eluf (float x) { return x >  0.f ? x : expm1f(x); }
__device__ __forceinline__ unsigned f2tf(float f) {
    unsigned u; asm("cvt.rna.tf32.f32 %0, %1;" : "=r"(u) : "f"(f)); return u;
}
__device__ __forceinline__ void mma_tf32(float* d, const unsigned* a, const unsigned* b) {
    asm volatile("mma.sync.aligned.m16n8k8.row.col.f32.tf32.tf32.f32 "
        "{%0,%1,%2,%3}, {%4,%5,%6,%7}, {%8,%9}, {%0,%1,%2,%3};\n"
        : "+f"(d[0]), "+f"(d[1]), "+f"(d[2]), "+f"(d[3])
        : "r"(a[0]), "r"(a[1]), "r"(a[2]), "r"(a[3]), "r"(b[0]), "r"(b[1]));
}

// ============================================================================
// k_wh: Wh = h @ W_heads[h], fused s1/s2 (unchanged from passing baseline)
// ============================================================================
__global__ __launch_bounds__(512) void k_wh(
    const float* __restrict__ hin, const float* __restrict__ W,
    const float* __restrict__ a1, const float* __restrict__ a2)
{
    __shared__ float sh[8][cFIN];
    __shared__ float red1[8][16], red2[8][16];
    const int row0 = blockIdx.x * 8;
    const int tid = threadIdx.x;

    for (int idx = tid; idx < 8 * cFIN; idx += 512) {
        int r = idx / cFIN, f = idx % cFIN;
        sh[r][f] = hin[(size_t)(row0 + r) * cFIN + f];
    }
    __syncthreads();

    const int hh = tid >> 6, d = tid & 63;
    float acc[8];
#pragma unroll
    for (int r = 0; r < 8; r++) acc[r] = 0.f;
    const float* Wp = W + (size_t)hh * cFIN * cD + d;
    for (int f = 0; f < cFIN; f++) {
        float w = Wp[(size_t)f * cD];
#pragma unroll
        for (int r = 0; r < 8; r++) acc[r] += sh[r][f] * w;
    }
    const float a1v = a1[hh * cD + d], a2v = a2[hh * cD + d];
    const int wrp = tid >> 5, lane = tid & 31;
#pragma unroll
    for (int r = 0; r < 8; r++) {
        int row = row0 + r;
        int b = row >> 7, n = row & 127;
        g_Wh[(((size_t)(b * cH + hh) * cN + n) << 6) + d] = acc[r];
        float v1 = acc[r] * a1v, v2 = acc[r] * a2v;
#pragma unroll
        for (int off = 16; off; off >>= 1) {
            v1 += __shfl_down_sync(0xffffffffu, v1, off);
            v2 += __shfl_down_sync(0xffffffffu, v2, off);
        }
        if (lane == 0) { red1[r][wrp] = v1; red2[r][wrp] = v2; }
    }
    __syncthreads();
    if (tid < 64) {
        int r = tid >> 3, h2 = tid & 7;
        int row = row0 + r;
        int b = row >> 7, n = row & 127;
        g_s1[(b * cH + h2) * cN + n] = red1[r][2 * h2] + red1[r][2 * h2 + 1];
        g_s2[(b * cH + h2) * cN + n] = red2[r][2 * h2] + red2[r][2 * h2 + 1];
    }
}

// ============================================================================
// k_attn1 (unchanged from passing baseline)
// ============================================================================
__global__ __launch_bounds__(256) void k_attn1(
    const float* __restrict__ edge, const int* __restrict__ adj,
    const float* __restrict__ ae)
{
    __shared__ float s1r[cN], s2r[cN];
    __shared__ float att_s[8][cN];
    __shared__ float whs[cN * cD];

    const int bid = blockIdx.x;
    const int b = bid >> 3, hh = bid & 7;
    const int tid = threadIdx.x, wrp = tid >> 5, lane = tid & 31;

    const float* whg = g_Wh + ((size_t)(b * cH + hh) * cN << 6);
    if (tid < cN) {
        s1r[tid] = g_s1[(b * cH + hh) * cN + tid];
        s2r[tid] = g_s2[(b * cH + hh) * cN + tid];
    }
    for (int idx = tid; idx < cN * cD; idx += 256) whs[idx] = whg[idx];
    __syncthreads();

    const float aev = ae[hh];
    const float2* whs2 = (const float2*)whs;
    for (int it = 0; it < 16; it++) {
        const int i = wrp * 16 + it;
        const float* erow = edge + ((size_t)b * cN + i) * cN;
        const int*   arow = adj  + ((size_t)b * cN + i) * cN;
        const float s1v = s1r[i];
        float val[4]; float mx = -3.4e38f;
#pragma unroll
        for (int k = 0; k < 4; k++) {
            int j = lane + 32 * k;
            float v = (arow[j] > 0) ? lrelu(s1v + s2r[j] + erow[j] * aev) : NEG_BIG_F;
            val[k] = v; mx = fmaxf(mx, v);
        }
#pragma unroll
        for (int off = 16; off; off >>= 1) mx = fmaxf(mx, __shfl_xor_sync(0xffffffffu, mx, off));
        float sum = 0.f;
#pragma unroll
        for (int k = 0; k < 4; k++) { val[k] = __expf(val[k] - mx); sum += val[k]; }
#pragma unroll
        for (int off = 16; off; off >>= 1) sum += __shfl_xor_sync(0xffffffffu, sum, off);
        const float inv = 1.f / sum;
#pragma unroll
        for (int k = 0; k < 4; k++) att_s[wrp][lane + 32 * k] = val[k] * inv;
        __syncwarp();

        float acc0 = 0.f, acc1 = 0.f;
#pragma unroll 8
        for (int j = 0; j < cN; j++) {
            float a = att_s[wrp][j];
            float2 wv = whs2[(j << 5) + lane];
            acc0 += a * wv.x; acc1 += a * wv.y;
        }
        float2 o; o.x = eluf(acc0); o.y = eluf(acc1);
        ((float2*)g_x)[(size_t)(b * cN + i) * (cHID / 2) + hh * 32 + lane] = o;
        __syncwarp();
    }
}

// ============================================================================
// gemm_tc: tf32 tensor-core GEMM, C[M,512] = A[M,512] @ B[512,512].
// 128x128 block tile, 8 warps (2x4), warp 64x32, mma m16n8k8, dbl-buffered.
// A smem pitch 136, column swizzled m^8 for k>=4 rows -> conflict-free loads.
// ============================================================================
__global__ __launch_bounds__(256, 1) void gemm_tc(
    const float* __restrict__ A, const float* __restrict__ B, float* __restrict__ C)
{
    __shared__ unsigned As[2][8 * 136];
    __shared__ unsigned Bs[2][8 * 136];
    const int t = threadIdx.x, lane = t & 31, wid = t >> 5;
    const int wm = wid >> 2, wn = wid & 3;
    const int m0 = blockIdx.y * 128, n0 = blockIdx.x * 128;

    const int lm = t >> 1, lw = (t & 1) * 4;       // A stage: row, k-base
    const int sc = lm ^ (lw ? 8 : 0);              // swizzled store column
    const int lk = t >> 5, ln = (t & 31) * 4;      // B stage

    float acc[4][4][4];
#pragma unroll
    for (int a = 0; a < 4; a++)
#pragma unroll
        for (int b = 0; b < 4; b++)
#pragma unroll
            for (int c = 0; c < 4; c++) acc[a][b][c] = 0.f;

    float4 av = *(const float4*)(A + (size_t)(m0 + lm) * 512 + lw);
    float4 bv = *(const float4*)(B + (size_t)lk * 512 + n0 + ln);
    {
        unsigned* Ad = As[0];
        Ad[(lw + 0) * 136 + sc] = f2tf(av.x);
        Ad[(lw + 1) * 136 + sc] = f2tf(av.y);
        Ad[(lw + 2) * 136 + sc] = f2tf(av.z);
        Ad[(lw + 3) * 136 + sc] = f2tf(av.w);
        uint4 bu = make_uint4(f2tf(bv.x), f2tf(bv.y), f2tf(bv.z), f2tf(bv.w));
        *(uint4*)(Bs[0] + lk * 136 + ln) = bu;
    }
    __syncthreads();

    const int kc = lane & 3, rg = lane >> 2;
    const int ar = wm * 64 + rg;
    const int bc = wn * 32 + rg;

    for (int s = 0; s < 64; s++) {
        const int cur = s & 1;
        if (s < 63) {
            int k0 = (s + 1) * 8;
            av = *(const float4*)(A + (size_t)(m0 + lm) * 512 + k0 + lw);
            bv = *(const float4*)(B + (size_t)(k0 + lk) * 512 + n0 + ln);
        }
        const unsigned* Ab = As[cur];
        const unsigned* Bb = Bs[cur];
        unsigned afr[4][4], bfr[4][2];
#pragma unroll
        for (int mt = 0; mt < 4; mt++) {
            int col = ar + mt * 16;
            afr[mt][0] = Ab[kc * 136 + col];
            afr[mt][1] = Ab[kc * 136 + col + 8];
            afr[mt][2] = Ab[(kc + 4) * 136 + col + 8];  // A[col][kc+4] (swz)
            afr[mt][3] = Ab[(kc + 4) * 136 + col];      // A[col+8][kc+4] (swz)
        }
#pragma unroll
        for (int nt = 0; nt < 4; nt++) {
            bfr[nt][0] = Bb[kc * 136 + bc + nt * 8];
            bfr[nt][1] = Bb[(kc + 4) * 136 + bc + nt * 8];
        }
#pragma unroll
        for (int mt = 0; mt < 4; mt++)
#pragma unroll
            for (int nt = 0; nt < 4; nt++)
                mma_tf32(acc[mt][nt], afr[mt], bfr[nt]);
        if (s < 63) {
            unsigned* Ad = As[cur ^ 1];
            Ad[(lw + 0) * 136 + sc] = f2tf(av.x);
            Ad[(lw + 1) * 136 + sc] = f2tf(av.y);
            Ad[(lw + 2) * 136 + sc] = f2tf(av.z);
            Ad[(lw + 3) * 136 + sc] = f2tf(av.w);
            uint4 bu = make_uint4(f2tf(bv.x), f2tf(bv.y), f2tf(bv.z), f2tf(bv.w));
            *(uint4*)(Bs[cur ^ 1] + lk * 136 + ln) = bu;
        }
        __syncthreads();
    }

#pragma unroll
    for (int mt = 0; mt < 4; mt++) {
        int row = m0 + wm * 64 + mt * 16 + rg;
#pragma unroll
        for (int nt = 0; nt < 4; nt++) {
            int col = n0 + wn * 32 + nt * 8 + 2 * kc;
            *(float2*)(C + (size_t)row * 512 + col) = make_float2(acc[mt][nt][0], acc[mt][nt][1]);
            *(float2*)(C + (size_t)(row + 8) * 512 + col) = make_float2(acc[mt][nt][2], acc[mt][nt][3]);
        }
    }
}

// ============================================================================
// k_t12 (unchanged)
// ============================================================================
__global__ __launch_bounds__(256) void k_t12(
    const float* __restrict__ a1o, const float* __restrict__ a2o)
{
    const int wrp = threadIdx.x >> 5, lane = threadIdx.x & 31;
    const int row = blockIdx.x * 8 + wrp;
    const float* x = g_Wx + (size_t)row * cHID;
    float t1 = 0.f, t2 = 0.f;
    for (int k = lane; k < cHID; k += 32) {
        float v = x[k];
        t1 += v * a1o[k]; t2 += v * a2o[k];
    }
#pragma unroll
    for (int off = 16; off; off >>= 1) {
        t1 += __shfl_down_sync(0xffffffffu, t1, off);
        t2 += __shfl_down_sync(0xffffffffu, t2, off);
    }
    if (lane == 0) { g_t1[row] = t1; g_t2[row] = t2; }
}

// ============================================================================
// k_attn2 (unchanged from passing baseline)
// ============================================================================
__global__ __launch_bounds__(256) void k_attn2(
    const float* __restrict__ edge, const int* __restrict__ adj,
    const float* __restrict__ ae_out)
{
    extern __shared__ float dynsm[];
    float* att2 = dynsm;
    float* wxs  = att2 + cN * cN;
    float* t1r  = wxs + cN * 64;
    float* t2r  = t1r + cN;
    float* csum = t2r + cN;

    const int b = blockIdx.x;
    const int tid = threadIdx.x, wrp = tid >> 5, lane = tid & 31;

    if (tid < cN) { t1r[tid] = g_t1[b * cN + tid]; t2r[tid] = g_t2[b * cN + tid]; }
    __syncthreads();
    const float aev = ae_out[0];

    for (int it = 0; it < 16; it++) {
        const int i = wrp * 16 + it;
        const float* erow = edge + ((size_t)b * cN + i) * cN;
        const int*   arow = adj  + ((size_t)b * cN + i) * cN;
        const float t1v = t1r[i];
        float val[4]; float mx = -3.4e38f;
#pragma unroll
        for (int k = 0; k < 4; k++) {
            int j = lane + 32 * k;
            float v = (arow[j] > 0) ? lrelu(t1v + t2r[j] + erow[j] * aev) : NEG_BIG_F;
            val[k] = v; mx = fmaxf(mx, v);
        }
#pragma unroll
        for (int off = 16; off; off >>= 1) mx = fmaxf(mx, __shfl_xor_sync(0xffffffffu, mx, off));
        float sum = 0.f;
#pragma unroll
        for (int k = 0; k < 4; k++) { val[k] = __expf(val[k] - mx); sum += val[k]; }
#pragma unroll
        for (int off = 16; off; off >>= 1) sum += __shfl_xor_sync(0xffffffffu, sum, off);
        const float inv = 1.f / sum;
#pragma unroll
        for (int k = 0; k < 4; k++) att2[i * cN + lane + 32 * k] = val[k] * inv;
    }
    __syncthreads();

    const int c2 = tid & 31, rg = tid >> 5;
    for (int dt = 0; dt < 8; dt++) {
        for (int idx = tid; idx < cN * 64; idx += 256) {
            int j = idx >> 6, c = idx & 63;
            wxs[idx] = g_Wx[(size_t)(b * cN + j) * cHID + dt * 64 + c];
        }
        __syncthreads();
        const float2* wxs2 = (const float2*)wxs;
        float cs0 = 0.f, cs1 = 0.f;
        for (int ii = 0; ii < 16; ii++) {
            const int i = rg * 16 + ii;
            const float* arow = att2 + i * cN;
            float acc0 = 0.f, acc1 = 0.f;
#pragma unroll 8
            for (int j = 0; j < cN; j++) {
                float a = arow[j];
                float2 wv = wxs2[(j << 5) + c2];
                acc0 += a * wv.x; acc1 += a * wv.y;
            }
            cs0 += eluf(acc0); cs1 += eluf(acc1);
        }
        csum[rg * 64 + 2 * c2]     = cs0;
        csum[rg * 64 + 2 * c2 + 1] = cs1;
        __syncthreads();
        if (tid < 64) {
            float tot = 0.f;
#pragma unroll
            for (int r = 0; r < 8; r++) tot += csum[r * 64 + tid];
            g_gat[b * cHID + dt * 64 + tid] = tot * (1.f / 128.f);
        }
        __syncthreads();
    }
}

// ============================================================================
// sgemm64: 64x64-tile fp32 GEMM, optional second (A2,B2) pair summed in,
// bias(+bias2), optional relu. 256 thr, 4x4 microtile.
// ============================================================================
__global__ __launch_bounds__(256) void sgemm64(
    const float* __restrict__ A,  const float* __restrict__ B,  int K,
    const float* __restrict__ A2, const float* __restrict__ B2, int K2,
    const float* __restrict__ bias, const float* __restrict__ bias2,
    float* __restrict__ C, int M, int Ncols, int act)
{
    __shared__ float As[8 * 68], Bs[8 * 68];
    const int m0 = blockIdx.y * 64, n0 = blockIdx.x * 64;
    const int t = threadIdx.x, tx = t & 15, ty = t >> 4;
    float acc[4][4];
#pragma unroll
    for (int i = 0; i < 4; i++)
#pragma unroll
        for (int j = 0; j < 4; j++) acc[i][j] = 0.f;

    for (int pass = 0; pass < 2; pass++) {
        const float* Ap = pass ? A2 : A;
        const float* Bp = pass ? B2 : B;
        const int Kp = pass ? K2 : K;
        if (Kp == 0) break;
        for (int k0 = 0; k0 < Kp; k0 += 8) {
#pragma unroll
            for (int i = 0; i < 2; i++) {
                int idx = t + i * 256;
                int m = idx >> 3, kk = idx & 7, gk = k0 + kk;
                As[kk * 68 + m] = (gk < Kp && m0 + m < M) ? Ap[(size_t)(m0 + m) * Kp + gk] : 0.f;
            }
#pragma unroll
            for (int i = 0; i < 2; i++) {
                int idx = t + i * 256;
                int kk = idx >> 6, n = idx & 63, gk = k0 + kk;
                Bs[kk * 68 + n] = (gk < Kp && n0 + n < Ncols) ? Bp[(size_t)gk * Ncols + n0 + n] : 0.f;
            }
            __syncthreads();
#pragma unroll
            for (int kk = 0; kk < 8; kk++) {
                float4 a4 = *(const float4*)(As + kk * 68 + ty * 4);
                float4 b4 = *(const float4*)(Bs + kk * 68 + tx * 4);
                float ar[4] = {a4.x, a4.y, a4.z, a4.w};
                float br[4] = {b4.x, b4.y, b4.z, b4.w};
#pragma unroll
                for (int i = 0; i < 4; i++)
#pragma unroll
                    for (int j = 0; j < 4; j++) acc[i][j] += ar[i] * br[j];
            }
            __syncthreads();
        }
    }
#pragma unroll
    for (int i = 0; i < 4; i++) {
        int gm = m0 + ty * 4 + i;
        if (gm >= M) continue;
#pragma unroll
        for (int j = 0; j < 4; j++) {
            int gn = n0 + tx * 4 + j;
            if (gn >= Ncols) continue;
            float v = acc[i][j];
            if (bias)  v += bias[gn];
            if (bias2) v += bias2[gn];
            if (act == 1) v = fmaxf(v, 0.f);
            C[(size_t)gm * Ncols + gn] = v;
        }
    }
}

// ============================================================================
// Host launcher
// ============================================================================
extern "C" void kernel_launch(void* const* d_in, const int* in_sizes, int n_in,
                              void* d_out, int out_size)
{
    const float* hin   = (const float*)d_in[0];
    const int*   adj   = (const int*)  d_in[1];
    const float* edge  = (const float*)d_in[2];
    const float* fp    = (const float*)d_in[3];
    const float* W_h   = (const float*)d_in[4];
    const float* a1_h  = (const float*)d_in[5];
    const float* a2_h  = (const float*)d_in[6];
    const float* ae_h  = (const float*)d_in[7];
    const float* W_out = (const float*)d_in[8];
    const float* a1_o  = (const float*)d_in[9];
    const float* a2_o  = (const float*)d_in[10];
    const float* ae_o  = (const float*)d_in[11];
    const float* fc1w  = (const float*)d_in[12];
    const float* fc1b  = (const float*)d_in[13];
    const float* fc2w  = (const float*)d_in[14];
    const float* fc2b  = (const float*)d_in[15];
    const float* q_w   = (const float*)d_in[16];
    const float* q_b   = (const float*)d_in[17];
    // d_in[18], d_in[19] = k_w, k_b : dead (softmax over size-1 axis == 1)
    const float* v_w   = (const float*)d_in[20];
    const float* v_b   = (const float*)d_in[21];
    const float* o_w   = (const float*)d_in[22];
    const float* o_b   = (const float*)d_in[23];
    const float* f1w   = (const float*)d_in[24];
    const float* f1b   = (const float*)d_in[25];
    const float* f2w   = (const float*)d_in[26];
    const float* f2b   = (const float*)d_in[27];
    float* out = (float*)d_out;

    float *pX, *pWx, *pGat, *pFp1, *pFpn, *pFused, *pZ1, *pZ2;
    cudaGetSymbolAddress((void**)&pX,    g_x);
    cudaGetSymbolAddress((void**)&pWx,   g_Wx);
    cudaGetSymbolAddress((void**)&pGat,  g_gat);
    cudaGetSymbolAddress((void**)&pFp1,  g_fp1);
    cudaGetSymbolAddress((void**)&pFpn,  g_fpn);
    cudaGetSymbolAddress((void**)&pFused,g_fused);
    cudaGetSymbolAddress((void**)&pZ1,   g_z1);
    cudaGetSymbolAddress((void**)&pZ2,   g_z2);

    const int smem_k4 = (cN * cN + cN * 64 + cN + cN + 8 * 64) * (int)sizeof(float);
    cudaFuncSetAttribute(k_attn2, cudaFuncAttributeMaxDynamicSharedMemorySize, smem_k4);

    // 1) Wh + s1/s2
    k_wh<<<(cB * cN) / 8, 512>>>(hin, W_h, a1_h, a2_h);
    // 2) head attention -> x [B,N,512]
    k_attn1<<<cB * cH, 256>>>(edge, adj, ae_h);
    // 3) Wx = x @ W_out  (tf32 tensor cores)
    gemm_tc<<<dim3(4, (cB * cN) / 128), 256>>>(pX, W_out, pWx);
    // 4) t1,t2
    k_t12<<<(cB * cN) / 8, 256>>>(a1_o, a2_o);
    // 5) output attention + ELU + mean -> gat_out [B,512]
    k_attn2<<<cB, 256, smem_k4>>>(edge, adj, ae_o);
    // 6) FPN + fusion + FFN tail (64x64 tiles; q/v fused as dual-GEMM)
    {
        dim3 g88(cHID / 64, cB / 64);
        sgemm64<<<g88, 256>>>(fp,   fc1w, cFPD, nullptr, nullptr, 0, fc1b, nullptr, pFp1, cB, cHID, 1);
        sgemm64<<<g88, 256>>>(pFp1, fc2w, cHID, nullptr, nullptr, 0, fc2b, nullptr, pFpn, cB, cHID, 0);
        sgemm64<<<g88, 256>>>(pGat, q_w,  cHID, pFpn, v_w, cHID, q_b, v_b, pFused, cB, cHID, 0);
        sgemm64<<<g88, 256>>>(pFused, o_w, cHID, nullptr, nullptr, 0, o_b, nullptr, pZ1, cB, cHID, 1);
        sgemm64<<<g88, 256>>>(pZ1, f1w, cHID, nullptr, nullptr, 0, f1b, nullptr, pZ2, cB, cHID, 1);
        sgemm64<<<dim3(1, cB / 64), 256>>>(pZ2, f2w, cHID, nullptr, nullptr, 0, f2b, nullptr, out, cB, cTASKS, 0);
    }
}